// round 3
// baseline (speedup 1.0000x reference)
#include <cuda_runtime.h>
#include <cuda_fp16.h>
#include <cstdint>

#define D_MODEL 1024
#define D_FF    8192
#define N_ELEM  64
#define D1      128
#define BATCH   2048

// fp16 scratch: w1 transposed to (j, e, d) contiguous-d; w2 kept (e, j, d) contiguous-d.
__device__ __align__(16) __half g_w1t[(size_t)D_FF * D_MODEL];
__device__ __align__(16) __half g_w2h[(size_t)D_FF * D_MODEL];
// relu(mid) scratch, layout [b][j]
__device__ float g_mid[(size_t)BATCH * D1];

// ---------------------------------------------------------------------------
// Prep (merged): blocks [0,4096) transpose+convert w1; blocks [4096,8192) convert w2.
// ---------------------------------------------------------------------------
__global__ __launch_bounds__(256) void prep_kernel(const float* __restrict__ w1,
                                                   const float* __restrict__ w2) {
    __shared__ float tile[32][65];
    const int t = threadIdx.x;
    if (blockIdx.x >= 4096) {
        const size_t i = ((size_t)(blockIdx.x - 4096) * 256 + t) * 8;
        float4 a = *reinterpret_cast<const float4*>(w2 + i);
        float4 b = *reinterpret_cast<const float4*>(w2 + i + 4);
        __half tmp[8];
        tmp[0] = __float2half_rn(a.x); tmp[1] = __float2half_rn(a.y);
        tmp[2] = __float2half_rn(a.z); tmp[3] = __float2half_rn(a.w);
        tmp[4] = __float2half_rn(b.x); tmp[5] = __float2half_rn(b.y);
        tmp[6] = __float2half_rn(b.z); tmp[7] = __float2half_rn(b.w);
        *reinterpret_cast<uint4*>(g_w2h + i) = *reinterpret_cast<const uint4*>(tmp);
        return;
    }
    const int d0  = (blockIdx.x & 31) * 32;
    const int je0 = (blockIdx.x >> 5) * 64;
    const int dr = t >> 5;
    const int c  = (t & 31) * 2;
#pragma unroll
    for (int r = 0; r < 32; r += 8) {
        float2 v = *reinterpret_cast<const float2*>(
            w1 + (size_t)(d0 + r + dr) * D_FF + je0 + c);
        tile[r + dr][c]     = v.x;
        tile[r + dr][c + 1] = v.y;
    }
    __syncthreads();
    const int jl = t >> 2;
    const int ds = (t & 3) * 8;
    __half tmp[8];
#pragma unroll
    for (int i = 0; i < 8; i++) tmp[i] = __float2half_rn(tile[ds + i][jl]);
    *reinterpret_cast<uint4*>(g_w1t + (size_t)(je0 + jl) * D_MODEL + d0 + ds) =
        *reinterpret_cast<const uint4*>(tmp);
}

// ---------------------------------------------------------------------------
// Phase A (grouped): grid = 16 b-tiles x 8 j-tiles = 128 CTAs, 256 threads.
// Tile: 128 samples x 16 j. Counting-sort samples by e per j; each used w1
// column loaded ONCE from L2 and dotted against all samples that chose it
// (avg ~2.3 samples/col here -> 128/55.5 reuse). x cached in smem as fp16,
// processed in two d-halves of 512. mid accumulated in smem fp32.
// ---------------------------------------------------------------------------
#define SMEM_XH    0                       // __half [128][512]   = 131072
#define SMEM_MID   131072                  // float  [16][128]    = 8192
#define SMEM_HIST  139264                  // u32    [16][64]     = 4096
#define SMEM_OFFS  143360                  // u16    [16][65]     = 2080
#define SMEM_SORT  145440                  // u8     [16][128]    = 2048
#define SMEM_MS    147488                  // u8     [16][128]    = 2048
#define SMEM_A_TOT 149536

__global__ __launch_bounds__(256) void phaseA_kernel(const int* __restrict__ qmask,
                                                     const float* __restrict__ x) {
    extern __shared__ char sm[];
    __half*         x_h     = reinterpret_cast<__half*>(sm + SMEM_XH);
    float*          mid_s   = reinterpret_cast<float*>(sm + SMEM_MID);
    unsigned*       hist    = reinterpret_cast<unsigned*>(sm + SMEM_HIST);
    unsigned short* offs    = reinterpret_cast<unsigned short*>(sm + SMEM_OFFS);
    unsigned char*  sortedb = reinterpret_cast<unsigned char*>(sm + SMEM_SORT);
    unsigned char*  ms8     = reinterpret_cast<unsigned char*>(sm + SMEM_MS);

    const int t = threadIdx.x, w = t >> 5, l = t & 31;
    const int bt = blockIdx.x >> 3, jt = blockIdx.x & 7;
    const int b0 = bt * 128, j0 = jt * 16;

    for (int i = t; i < 16 * 64; i += 256) hist[i] = 0u;
    for (int i = t; i < 16 * 128; i += 256) mid_s[i] = 0.f;
    __syncthreads();

    // load masks + histogram (idx = b*16 + jj)
#pragma unroll
    for (int k = 0; k < 8; k++) {
        int idx = t * 8 + k;
        int jj = idx & 15, b = idx >> 4;
        int m = qmask[(size_t)(b0 + b) * D1 + j0 + jj];
        ms8[jj * 128 + b] = (unsigned char)m;
        atomicAdd(&hist[jj * 64 + m], 1u);
    }
    __syncthreads();

    // per-j exclusive scan over 64 buckets (warp w -> jj = 2w, 2w+1)
#pragma unroll
    for (int q = 0; q < 2; q++) {
        int jj = 2 * w + q;
        unsigned v0 = hist[jj * 64 + l], v1 = hist[jj * 64 + 32 + l];
        unsigned s0 = v0, s1 = v1;
#pragma unroll
        for (int o = 1; o < 32; o <<= 1) {
            unsigned a = __shfl_up_sync(0xffffffffu, s0, o);
            unsigned b = __shfl_up_sync(0xffffffffu, s1, o);
            if (l >= o) { s0 += a; s1 += b; }
        }
        unsigned tot0 = __shfl_sync(0xffffffffu, s0, 31);
        unsigned e0 = s0 - v0;
        unsigned e1 = tot0 + s1 - v1;
        offs[jj * 65 + l]      = (unsigned short)e0;
        offs[jj * 65 + 32 + l] = (unsigned short)e1;
        if (l == 31) offs[jj * 65 + 64] = 128;
        hist[jj * 64 + l]      = e0;   // reuse as scatter cursor
        hist[jj * 64 + 32 + l] = e1;
    }
    __syncthreads();

    // scatter: sortedb[jj] = sample indices grouped by e
#pragma unroll
    for (int k = 0; k < 8; k++) {
        int idx = t * 8 + k;
        int jj = idx & 15, b = idx >> 4;
        int m = ms8[jj * 128 + b];
        unsigned pos = atomicAdd(&hist[jj * 64 + m], 1u);
        sortedb[jj * 128 + pos] = (unsigned char)b;
    }
    __syncthreads();

    // two d-halves of 512
    for (int h = 0; h < 2; h++) {
        // stage x half as fp16: [b][d] rows of 512 halves
        {
            const float4* xg = reinterpret_cast<const float4*>(
                x + (size_t)b0 * D_MODEL + h * 512);
            for (int i = t; i < 128 * 128; i += 256) {
                int b = i >> 7, p = i & 127;
                float4 v = xg[(size_t)b * 256 + p];
                __half2 h0 = __floats2half2_rn(v.x, v.y);
                __half2 h1 = __floats2half2_rn(v.z, v.w);
                uint2 u;
                u.x = *reinterpret_cast<unsigned*>(&h0);
                u.y = *reinterpret_cast<unsigned*>(&h1);
                *reinterpret_cast<uint2*>(x_h + b * 512 + p * 4) = u;
            }
        }
        __syncthreads();

#pragma unroll
        for (int q = 0; q < 2; q++) {
            const int jj = 2 * w + q;
            const int jg = j0 + jj;
            const __half* colbase = g_w1t + ((size_t)jg * N_ELEM) * D_MODEL + h * 512;
            const unsigned short* po = offs + jj * 65;
            const unsigned char*  sb = sortedb + jj * 128;
            float* msl = mid_s + jj * 128;
            int start = 0;
            for (int e = 0; e < 64; e++) {
                int end = po[e + 1];
                if (end == start) continue;
                // load column half (512 halves): lane l holds d = 4l..4l+3 (+128k)
                const uint2* cp = reinterpret_cast<const uint2*>(colbase + (size_t)e * 1024);
                uint2 ca = cp[l], cb = cp[l + 32], cc = cp[l + 64], cd = cp[l + 96];
                __half2 c0 = *reinterpret_cast<__half2*>(&ca.x);
                __half2 c1 = *reinterpret_cast<__half2*>(&ca.y);
                __half2 c2 = *reinterpret_cast<__half2*>(&cb.x);
                __half2 c3 = *reinterpret_cast<__half2*>(&cb.y);
                __half2 c4 = *reinterpret_cast<__half2*>(&cc.x);
                __half2 c5 = *reinterpret_cast<__half2*>(&cc.y);
                __half2 c6 = *reinterpret_cast<__half2*>(&cd.x);
                __half2 c7 = *reinterpret_cast<__half2*>(&cd.y);
                for (int p = start; p < end; p++) {
                    int b = sb[p];
                    const uint2* xb = reinterpret_cast<const uint2*>(x_h + b * 512);
                    uint2 x0 = xb[l], x1 = xb[l + 32], x2 = xb[l + 64], x3 = xb[l + 96];
                    // two HFMA2 chains of length 4, flushed to fp32
                    __half2 accA = __hmul2(c0, *reinterpret_cast<__half2*>(&x0.x));
                    __half2 accB = __hmul2(c1, *reinterpret_cast<__half2*>(&x0.y));
                    accA = __hfma2(c2, *reinterpret_cast<__half2*>(&x1.x), accA);
                    accB = __hfma2(c3, *reinterpret_cast<__half2*>(&x1.y), accB);
                    accA = __hfma2(c4, *reinterpret_cast<__half2*>(&x2.x), accA);
                    accB = __hfma2(c5, *reinterpret_cast<__half2*>(&x2.y), accB);
                    accA = __hfma2(c6, *reinterpret_cast<__half2*>(&x3.x), accA);
                    accB = __hfma2(c7, *reinterpret_cast<__half2*>(&x3.y), accB);
                    float2 fa = __half22float2(accA);
                    float2 fb = __half22float2(accB);
                    float s = (fa.x + fb.x) + (fa.y + fb.y);
#pragma unroll
                    for (int o = 16; o > 0; o >>= 1)
                        s += __shfl_xor_sync(0xffffffffu, s, o);
                    if (l == 0) msl[b] += s;
                }
                start = end;
            }
        }
        __syncthreads();
    }

    // write relu(mid)
    for (int i = t; i < 16 * 128; i += 256) {
        int jj = i & 15, b = i >> 4;
        g_mid[(size_t)(b0 + b) * D1 + j0 + jj] = fmaxf(mid_s[jj * 128 + b], 0.f);
    }
}

// ---------------------------------------------------------------------------
// Phase B: per-sample CTA (2048 x 256). Warp owns 128-float res slice; loops
// all 128 j with warp-uniform relu skip (~50%).
// ---------------------------------------------------------------------------
__global__ __launch_bounds__(256) void phaseB_kernel(const int* __restrict__ qmask,
                                                     const float* __restrict__ b2,
                                                     float* __restrict__ out_res,
                                                     float* __restrict__ out_mask) {
    __shared__ float midr[D1];
    __shared__ int   ms[D1];
    const int b = blockIdx.x, t = threadIdx.x, w = t >> 5, l = t & 31;

    if (t < D1) {
        int m = qmask[(size_t)b * D1 + t];
        ms[t] = m;
        midr[t] = g_mid[(size_t)b * D1 + t];
        if (out_mask) out_mask[(size_t)b * D1 + t] = (float)m;
    }
    __syncthreads();

    const int base = w * 128 + l * 4;
    float a0 = 0.f, a1 = 0.f, a2 = 0.f, a3 = 0.f;
#pragma unroll 4
    for (int j = 0; j < D1; j++) {
        const float r = midr[j];
        if (r > 0.f) {
            const int m = ms[j];
            uint2 hv = *reinterpret_cast<const uint2*>(
                g_w2h + ((size_t)m * D1 + j) * D_MODEL + base);
            __half2 h0 = *reinterpret_cast<const __half2*>(&hv.x);
            __half2 h1 = *reinterpret_cast<const __half2*>(&hv.y);
            float2 f0 = __half22float2(h0);
            float2 f1 = __half22float2(h1);
            a0 = fmaf(r, f0.x, a0);
            a1 = fmaf(r, f0.y, a1);
            a2 = fmaf(r, f1.x, a2);
            a3 = fmaf(r, f1.y, a3);
        }
    }

    float4 bv = reinterpret_cast<const float4*>(b2)[base >> 2];
    float4 o;
    o.x = a0 + bv.x; o.y = a1 + bv.y; o.z = a2 + bv.z; o.w = a3 + bv.w;
    reinterpret_cast<float4*>(out_res + (size_t)b * D_MODEL)[base >> 2] = o;
}

// ---------------------------------------------------------------------------
extern "C" void kernel_launch(void* const* d_in, const int* in_sizes, int n_in,
                              void* d_out, int out_size) {
    const int*   qmask = nullptr;
    const float* x = nullptr, *w1 = nullptr, *w2 = nullptr, *b2 = nullptr;
    for (int i = 0; i < n_in; i++) {
        const int sz = in_sizes[i];
        if (sz == BATCH * D1)            qmask = (const int*)d_in[i];
        else if (sz == BATCH * D_MODEL)  x     = (const float*)d_in[i];
        else if (sz == D_MODEL)          b2    = (const float*)d_in[i];
        else if (sz == D_MODEL * D_FF) {
            if (!w1) w1 = (const float*)d_in[i];
            else     w2 = (const float*)d_in[i];
        }
    }

    float* out      = (float*)d_out;
    float* out_mask = nullptr;
    float* out_res  = out;
    if (out_size >= BATCH * D1 + BATCH * D_MODEL) {
        out_mask = out;
        out_res  = out + BATCH * D1;
    }

    cudaFuncSetAttribute(phaseA_kernel,
                         cudaFuncAttributeMaxDynamicSharedMemorySize, SMEM_A_TOT);

    prep_kernel<<<8192, 256>>>(w1, w2);
    phaseA_kernel<<<128, 256, SMEM_A_TOT>>>(qmask, x);
    phaseB_kernel<<<2048, 256>>>(qmask, b2, out_res, out_mask);
}

// round 4
// speedup vs baseline: 1.6325x; 1.6325x over previous
#include <cuda_runtime.h>
#include <cuda_fp16.h>
#include <cstdint>

#define D_MODEL 1024
#define D_FF    8192
#define N_ELEM  64
#define D1      128
#define BATCH   2048

__device__ __align__(16) __half g_w1t[(size_t)D_FF * D_MODEL];
__device__ __align__(16) __half g_w2h[(size_t)D_FF * D_MODEL];
__device__ float g_mid[(size_t)BATCH * D1];

// ---------------------------------------------------------------------------
// Prep (merged): blocks [0,4096) transpose+convert w1; [4096,8192) convert w2.
// ---------------------------------------------------------------------------
__global__ __launch_bounds__(256) void prep_kernel(const float* __restrict__ w1,
                                                   const float* __restrict__ w2) {
    __shared__ float tile[32][65];
    const int t = threadIdx.x;
    if (blockIdx.x >= 4096) {
        const size_t i = ((size_t)(blockIdx.x - 4096) * 256 + t) * 8;
        float4 a = *reinterpret_cast<const float4*>(w2 + i);
        float4 b = *reinterpret_cast<const float4*>(w2 + i + 4);
        __half tmp[8];
        tmp[0] = __float2half_rn(a.x); tmp[1] = __float2half_rn(a.y);
        tmp[2] = __float2half_rn(a.z); tmp[3] = __float2half_rn(a.w);
        tmp[4] = __float2half_rn(b.x); tmp[5] = __float2half_rn(b.y);
        tmp[6] = __float2half_rn(b.z); tmp[7] = __float2half_rn(b.w);
        *reinterpret_cast<uint4*>(g_w2h + i) = *reinterpret_cast<const uint4*>(tmp);
        return;
    }
    const int d0  = (blockIdx.x & 31) * 32;
    const int je0 = (blockIdx.x >> 5) * 64;
    const int dr = t >> 5;
    const int c  = (t & 31) * 2;
#pragma unroll
    for (int r = 0; r < 32; r += 8) {
        float2 v = *reinterpret_cast<const float2*>(
            w1 + (size_t)(d0 + r + dr) * D_FF + je0 + c);
        tile[r + dr][c]     = v.x;
        tile[r + dr][c + 1] = v.y;
    }
    __syncthreads();
    const int jl = t >> 2;
    const int ds = (t & 3) * 8;
    __half tmp[8];
#pragma unroll
    for (int i = 0; i < 8; i++) tmp[i] = __float2half_rn(tile[ds + i][jl]);
    *reinterpret_cast<uint4*>(g_w1t + (size_t)(je0 + jl) * D_MODEL + d0 + ds) =
        *reinterpret_cast<const uint4*>(tmp);
}

// ---------------------------------------------------------------------------
// Phase A v2: 128 CTAs (16 b-tiles x 8 j-tiles), 512 threads (16 warps).
// Warp w owns j = j0 + w. Counting-sort samples by e, compact used-column
// list, column loaded once per d-half (2x LDG.128/lane), samples processed
// in PAIRS with a 5-shuffle dual butterfly. x staged fp16 in smem per half.
// ---------------------------------------------------------------------------
#define SMEM_XH    0                       // __half [128][512]  = 131072
#define SMEM_MID   131072                  // float  [16][128]   = 8192
#define SMEM_HIST  139264                  // u32    [16][64]    = 4096
#define SMEM_OFFS  143360                  // u16    [16][65]    = 2080 (pad 2080->2080)
#define SMEM_SORT  145440                  // u8     [16][128]   = 2048
#define SMEM_MS    147488                  // u8     [16][128]   = 2048
#define SMEM_COL   149536                  // u8     [16][64]    = 1024
#define SMEM_NC    150560                  // u32    [16]        = 64
#define SMEM_A_TOT 150624

__global__ __launch_bounds__(512) void phaseA_kernel(const int* __restrict__ qmask,
                                                     const float* __restrict__ x) {
    extern __shared__ char sm[];
    __half*         x_h     = reinterpret_cast<__half*>(sm + SMEM_XH);
    float*          mid_s   = reinterpret_cast<float*>(sm + SMEM_MID);
    unsigned*       hist    = reinterpret_cast<unsigned*>(sm + SMEM_HIST);
    unsigned short* offs    = reinterpret_cast<unsigned short*>(sm + SMEM_OFFS);
    unsigned char*  sortedb = reinterpret_cast<unsigned char*>(sm + SMEM_SORT);
    unsigned char*  ms8     = reinterpret_cast<unsigned char*>(sm + SMEM_MS);
    unsigned char*  colist  = reinterpret_cast<unsigned char*>(sm + SMEM_COL);
    unsigned*       ncols_s = reinterpret_cast<unsigned*>(sm + SMEM_NC);

    const int t = threadIdx.x, w = t >> 5, l = t & 31;
    const int bt = blockIdx.x >> 3, jt = blockIdx.x & 7;
    const int b0 = bt * 128, j0 = jt * 16;

    for (int i = t; i < 16 * 64; i += 512) hist[i] = 0u;
    for (int i = t; i < 16 * 128; i += 512) mid_s[i] = 0.f;
    __syncthreads();

    // masks + histogram: thread t -> sample b = t>>2, 4 consecutive j
    {
        const int b = t >> 2;
        const int jq = (t & 3) * 4;
        int4 mm = reinterpret_cast<const int4*>(
            qmask + (size_t)(b0 + b) * D1 + j0)[t & 3];
        int mv[4] = {mm.x, mm.y, mm.z, mm.w};
#pragma unroll
        for (int k = 0; k < 4; k++) {
            int jj = jq + k, m = mv[k];
            ms8[jj * 128 + b] = (unsigned char)m;
            atomicAdd(&hist[jj * 64 + m], 1u);
        }
    }
    __syncthreads();

    // per-j exclusive scan (warp w -> j=w) + compact column list
    {
        const int jj = w;
        unsigned v0 = hist[jj * 64 + l], v1 = hist[jj * 64 + 32 + l];
        unsigned s0 = v0, s1 = v1;
#pragma unroll
        for (int o = 1; o < 32; o <<= 1) {
            unsigned a = __shfl_up_sync(0xffffffffu, s0, o);
            unsigned b = __shfl_up_sync(0xffffffffu, s1, o);
            if (l >= o) { s0 += a; s1 += b; }
        }
        unsigned tot0 = __shfl_sync(0xffffffffu, s0, 31);
        unsigned e0 = s0 - v0;
        unsigned e1 = tot0 + s1 - v1;
        offs[jj * 65 + l]      = (unsigned short)e0;
        offs[jj * 65 + 32 + l] = (unsigned short)e1;
        if (l == 31) offs[jj * 65 + 64] = 128;
        hist[jj * 64 + l]      = e0;   // scatter cursors
        hist[jj * 64 + 32 + l] = e1;
        // compact list of used columns
        unsigned bal0 = __ballot_sync(0xffffffffu, v0 > 0);
        unsigned bal1 = __ballot_sync(0xffffffffu, v1 > 0);
        unsigned n0 = __popc(bal0);
        if (v0 > 0) colist[jj * 64 + __popc(bal0 & ((1u << l) - 1u))] = (unsigned char)l;
        if (v1 > 0) colist[jj * 64 + n0 + __popc(bal1 & ((1u << l) - 1u))] =
            (unsigned char)(32 + l);
        if (l == 0) ncols_s[jj] = n0 + __popc(bal1);
    }
    __syncthreads();

    // scatter sample ids grouped by e
    {
        const int b = t >> 2;
        const int jq = (t & 3) * 4;
#pragma unroll
        for (int k = 0; k < 4; k++) {
            int jj = jq + k;
            int m = ms8[jj * 128 + b];
            unsigned pos = atomicAdd(&hist[jj * 64 + m], 1u);
            sortedb[jj * 128 + pos] = (unsigned char)b;
        }
    }
    __syncthreads();

    // two d-halves of 512
    for (int h = 0; h < 2; h++) {
        // stage x half as fp16
        {
            const float4* xg = reinterpret_cast<const float4*>(x);
            for (int i = t; i < 128 * 128; i += 512) {
                int b = i >> 7, p = i & 127;
                float4 v = xg[(size_t)(b0 + b) * 256 + h * 128 + p];
                __half2 h0 = __floats2half2_rn(v.x, v.y);
                __half2 h1 = __floats2half2_rn(v.z, v.w);
                uint2 u;
                u.x = *reinterpret_cast<unsigned*>(&h0);
                u.y = *reinterpret_cast<unsigned*>(&h1);
                *reinterpret_cast<uint2*>(x_h + b * 512 + p * 4) = u;
            }
        }
        __syncthreads();

        {
            const int jj = w;
            const __half* colbase =
                g_w1t + ((size_t)(j0 + jj) * N_ELEM) * D_MODEL + h * 512;
            const unsigned short* po = offs + jj * 65;
            const unsigned char*  sb = sortedb + jj * 128;
            float* msl = mid_s + jj * 128;
            const int nc = (int)ncols_s[jj];

            for (int i = 0; i < nc; i++) {
                const int e = colist[jj * 64 + i];
                const int start = po[e], end = po[e + 1];
                const uint4* cp =
                    reinterpret_cast<const uint4*>(colbase + (size_t)e * 1024);
                uint4 ca = cp[l], cb = cp[l + 32];
                const __half2* c0 = reinterpret_cast<const __half2*>(&ca);
                const __half2* c1 = reinterpret_cast<const __half2*>(&cb);

#define DOT_SAMPLE(bS, sOut)                                                   \
                {                                                              \
                    const uint4* xb =                                          \
                        reinterpret_cast<const uint4*>(x_h + (bS) * 512);      \
                    uint4 xa = xb[l], xc = xb[l + 32];                         \
                    const __half2* h0 = reinterpret_cast<const __half2*>(&xa); \
                    const __half2* h1 = reinterpret_cast<const __half2*>(&xc); \
                    __half2 accA = __hmul2(c0[0], h0[0]);                      \
                    __half2 accB = __hmul2(c0[1], h0[1]);                      \
                    accA = __hfma2(c0[2], h0[2], accA);                        \
                    accB = __hfma2(c0[3], h0[3], accB);                        \
                    accA = __hfma2(c1[0], h1[0], accA);                        \
                    accB = __hfma2(c1[1], h1[1], accB);                        \
                    accA = __hfma2(c1[2], h1[2], accA);                        \
                    accB = __hfma2(c1[3], h1[3], accB);                        \
                    float2 fa = __half22float2(accA);                          \
                    float2 fb = __half22float2(accB);                          \
                    sOut = (fa.x + fb.x) + (fa.y + fb.y);                      \
                }

                int p = start;
                for (; p + 1 < end; p += 2) {
                    const int bA = sb[p], bB = sb[p + 1];
                    float s0, s1;
                    DOT_SAMPLE(bA, s0);
                    DOT_SAMPLE(bB, s1);
                    // dual butterfly: lane0 -> sum(s0), lane1 -> sum(s1)
                    float v   = (l & 1) ? s1 : s0;
                    float oth = (l & 1) ? s0 : s1;
                    v += __shfl_xor_sync(0xffffffffu, oth, 1);
                    v += __shfl_xor_sync(0xffffffffu, v, 2);
                    v += __shfl_xor_sync(0xffffffffu, v, 4);
                    v += __shfl_xor_sync(0xffffffffu, v, 8);
                    v += __shfl_xor_sync(0xffffffffu, v, 16);
                    if (l < 2) msl[(l == 0) ? bA : bB] += v;
                }
                if (p < end) {
                    const int bA = sb[p];
                    float s;
                    DOT_SAMPLE(bA, s);
#pragma unroll
                    for (int o = 16; o > 0; o >>= 1)
                        s += __shfl_xor_sync(0xffffffffu, s, o);
                    if (l == 0) msl[bA] += s;
                }
#undef DOT_SAMPLE
            }
        }
        __syncthreads();
    }

    // write relu(mid), coalesced over j
    for (int i = t; i < 16 * 128; i += 512) {
        int jj = i & 15, b = i >> 4;
        g_mid[(size_t)(b0 + b) * D1 + j0 + jj] = fmaxf(mid_s[jj * 128 + b], 0.f);
    }
}

// ---------------------------------------------------------------------------
// Phase B: per-sample CTA (2048 x 256). Warp owns a 128-float res slice,
// loops all 128 j with warp-uniform relu skip (~50%).
// ---------------------------------------------------------------------------
__global__ __launch_bounds__(256) void phaseB_kernel(const int* __restrict__ qmask,
                                                     const float* __restrict__ b2,
                                                     float* __restrict__ out_res,
                                                     float* __restrict__ out_mask) {
    __shared__ float midr[D1];
    __shared__ int   ms[D1];
    const int b = blockIdx.x, t = threadIdx.x, w = t >> 5, l = t & 31;

    if (t < D1) {
        int m = qmask[(size_t)b * D1 + t];
        ms[t] = m;
        midr[t] = g_mid[(size_t)b * D1 + t];
        if (out_mask) out_mask[(size_t)b * D1 + t] = (float)m;
    }
    __syncthreads();

    const int base = w * 128 + l * 4;
    float a0 = 0.f, a1 = 0.f, a2 = 0.f, a3 = 0.f;
#pragma unroll 4
    for (int j = 0; j < D1; j++) {
        const float r = midr[j];
        if (r > 0.f) {
            const int m = ms[j];
            uint2 hv = *reinterpret_cast<const uint2*>(
                g_w2h + ((size_t)m * D1 + j) * D_MODEL + base);
            __half2 h0 = *reinterpret_cast<const __half2*>(&hv.x);
            __half2 h1 = *reinterpret_cast<const __half2*>(&hv.y);
            float2 f0 = __half22float2(h0);
            float2 f1 = __half22float2(h1);
            a0 = fmaf(r, f0.x, a0);
            a1 = fmaf(r, f0.y, a1);
            a2 = fmaf(r, f1.x, a2);
            a3 = fmaf(r, f1.y, a3);
        }
    }

    float4 bv = reinterpret_cast<const float4*>(b2)[base >> 2];
    float4 o;
    o.x = a0 + bv.x; o.y = a1 + bv.y; o.z = a2 + bv.z; o.w = a3 + bv.w;
    reinterpret_cast<float4*>(out_res + (size_t)b * D_MODEL)[base >> 2] = o;
}

// ---------------------------------------------------------------------------
extern "C" void kernel_launch(void* const* d_in, const int* in_sizes, int n_in,
                              void* d_out, int out_size) {
    const int*   qmask = nullptr;
    const float* x = nullptr, *w1 = nullptr, *w2 = nullptr, *b2 = nullptr;
    for (int i = 0; i < n_in; i++) {
        const int sz = in_sizes[i];
        if (sz == BATCH * D1)            qmask = (const int*)d_in[i];
        else if (sz == BATCH * D_MODEL)  x     = (const float*)d_in[i];
        else if (sz == D_MODEL)          b2    = (const float*)d_in[i];
        else if (sz == D_MODEL * D_FF) {
            if (!w1) w1 = (const float*)d_in[i];
            else     w2 = (const float*)d_in[i];
        }
    }

    float* out      = (float*)d_out;
    float* out_mask = nullptr;
    float* out_res  = out;
    if (out_size >= BATCH * D1 + BATCH * D_MODEL) {
        out_mask = out;
        out_res  = out + BATCH * D1;
    }

    cudaFuncSetAttribute(phaseA_kernel,
                         cudaFuncAttributeMaxDynamicSharedMemorySize, SMEM_A_TOT);

    prep_kernel<<<8192, 256>>>(w1, w2);
    phaseA_kernel<<<128, 512, SMEM_A_TOT>>>(qmask, x);
    phaseB_kernel<<<2048, 256>>>(qmask, b2, out_res, out_mask);
}

// round 5
// speedup vs baseline: 2.7360x; 1.6759x over previous
#include <cuda_runtime.h>
#include <cuda_fp16.h>
#include <cstdint>

#define D_MODEL 1024
#define D_FF    8192
#define N_ELEM  64
#define D1      128
#define BATCH   2048

__device__ __align__(16) __half g_w1t[(size_t)D_FF * D_MODEL];
__device__ __align__(16) __half g_w2h[(size_t)D_FF * D_MODEL];

// ---------------------------------------------------------------------------
// Prep (merged): blocks [0,4096) transpose+convert w1; [4096,8192) convert w2.
// ---------------------------------------------------------------------------
__global__ __launch_bounds__(256) void prep_kernel(const float* __restrict__ w1,
                                                   const float* __restrict__ w2) {
    __shared__ float tile[32][65];
    const int t = threadIdx.x;
    if (blockIdx.x >= 4096) {
        const size_t i = ((size_t)(blockIdx.x - 4096) * 256 + t) * 8;
        float4 a = *reinterpret_cast<const float4*>(w2 + i);
        float4 b = *reinterpret_cast<const float4*>(w2 + i + 4);
        __half tmp[8];
        tmp[0] = __float2half_rn(a.x); tmp[1] = __float2half_rn(a.y);
        tmp[2] = __float2half_rn(a.z); tmp[3] = __float2half_rn(a.w);
        tmp[4] = __float2half_rn(b.x); tmp[5] = __float2half_rn(b.y);
        tmp[6] = __float2half_rn(b.z); tmp[7] = __float2half_rn(b.w);
        *reinterpret_cast<uint4*>(g_w2h + i) = *reinterpret_cast<const uint4*>(tmp);
        return;
    }
    const int d0  = (blockIdx.x & 31) * 32;
    const int je0 = (blockIdx.x >> 5) * 64;
    const int dr = t >> 5;
    const int c  = (t & 31) * 2;
#pragma unroll
    for (int r = 0; r < 32; r += 8) {
        float2 v = *reinterpret_cast<const float2*>(
            w1 + (size_t)(d0 + r + dr) * D_FF + je0 + c);
        tile[r + dr][c]     = v.x;
        tile[r + dr][c + 1] = v.y;
    }
    __syncthreads();
    const int jl = t >> 2;
    const int ds = (t & 3) * 8;
    __half tmp[8];
#pragma unroll
    for (int i = 0; i < 8; i++) tmp[i] = __float2half_rn(tile[ds + i][jl]);
    *reinterpret_cast<uint4*>(g_w1t + (size_t)(je0 + jl) * D_MODEL + d0 + ds) =
        *reinterpret_cast<const uint4*>(tmp);
}

// ---------------------------------------------------------------------------
// Fused main kernel: one CTA per sample, 256 threads (8 warps).
// Phase A: warp w computes j = w*16 .. w*16+15 in pairs (p, p+8).
//   x cached in smem fp16, hoisted into 4 uint4 regs per lane (reused all j).
//   Column = 4x LDG.128 per lane. Dot = 16 HFMA2 (4 accs, chain 4), fp16
//   tail adds, dual-butterfly reduces a pair of j with 5 shuffles.
// Phase B: warps 0-3 handle j<64, warps 4-7 handle j>=64; lane owns 8 floats
//   (LDG.128 per j, relu-skip warp-uniform). Halves combined via smem.
// ---------------------------------------------------------------------------
__global__ __launch_bounds__(256) void fused_kernel(
    const int*   __restrict__ qmask,
    const float* __restrict__ x,
    const float* __restrict__ b2,
    float*       __restrict__ out_res,
    float*       __restrict__ out_mask)
{
    __shared__ __align__(16) __half x_h[D_MODEL];   // 2 KB
    __shared__ float midr[D1];
    __shared__ int   ms[D1];
    __shared__ __align__(16) float res_s[D_MODEL];  // 4 KB

    const int b = blockIdx.x;
    const int t = threadIdx.x;
    const int w = t >> 5;
    const int l = t & 31;

    // stage x as fp16 + masks
    {
        float4 v = reinterpret_cast<const float4*>(x + (size_t)b * D_MODEL)[t];
        __half2 h0 = __floats2half2_rn(v.x, v.y);
        __half2 h1 = __floats2half2_rn(v.z, v.w);
        uint2 u;
        u.x = *reinterpret_cast<unsigned*>(&h0);
        u.y = *reinterpret_cast<unsigned*>(&h1);
        *reinterpret_cast<uint2*>(x_h + t * 4) = u;
    }
    if (t < D1) {
        int m = qmask[(size_t)b * D1 + t];
        ms[t] = m;
        if (out_mask) out_mask[(size_t)b * D1 + t] = (float)m;
    }
    __syncthreads();

    // ---- Phase A ----
    {
        const uint4* xh4 = reinterpret_cast<const uint4*>(x_h);
        const uint4 xv0 = xh4[l], xv1 = xh4[l + 32], xv2 = xh4[l + 64], xv3 = xh4[l + 96];
        const __half2* xA = reinterpret_cast<const __half2*>(&xv0);
        const __half2* xB = reinterpret_cast<const __half2*>(&xv1);
        const __half2* xC = reinterpret_cast<const __half2*>(&xv2);
        const __half2* xD = reinterpret_cast<const __half2*>(&xv3);

#define DOT16(cp, sOut)                                                        \
        {                                                                      \
            uint4 u0 = (cp)[l], u1 = (cp)[l + 32], u2 = (cp)[l + 64],          \
                  u3 = (cp)[l + 96];                                           \
            const __half2* cA = reinterpret_cast<const __half2*>(&u0);         \
            const __half2* cB = reinterpret_cast<const __half2*>(&u1);         \
            const __half2* cC = reinterpret_cast<const __half2*>(&u2);         \
            const __half2* cD = reinterpret_cast<const __half2*>(&u3);         \
            __half2 a0 = __hmul2(cA[0], xA[0]);                                \
            __half2 a1 = __hmul2(cA[1], xA[1]);                                \
            __half2 a2 = __hmul2(cA[2], xA[2]);                                \
            __half2 a3 = __hmul2(cA[3], xA[3]);                                \
            a0 = __hfma2(cB[0], xB[0], a0);                                    \
            a1 = __hfma2(cB[1], xB[1], a1);                                    \
            a2 = __hfma2(cB[2], xB[2], a2);                                    \
            a3 = __hfma2(cB[3], xB[3], a3);                                    \
            a0 = __hfma2(cC[0], xC[0], a0);                                    \
            a1 = __hfma2(cC[1], xC[1], a1);                                    \
            a2 = __hfma2(cC[2], xC[2], a2);                                    \
            a3 = __hfma2(cC[3], xC[3], a3);                                    \
            a0 = __hfma2(cD[0], xD[0], a0);                                    \
            a1 = __hfma2(cD[1], xD[1], a1);                                    \
            a2 = __hfma2(cD[2], xD[2], a2);                                    \
            a3 = __hfma2(cD[3], xD[3], a3);                                    \
            float2 f0 = __half22float2(a0);                                    \
            float2 f1 = __half22float2(a1);                                    \
            float2 f2 = __half22float2(a2);                                    \
            float2 f3 = __half22float2(a3);                                    \
            sOut = ((f0.x + f0.y) + (f1.x + f1.y)) +                           \
                   ((f2.x + f2.y) + (f3.x + f3.y));                            \
        }

#pragma unroll
        for (int p = 0; p < 8; p++) {
            const int jA = w * 16 + p;
            const int jB = jA + 8;
            const uint4* cpA = reinterpret_cast<const uint4*>(
                g_w1t + (((size_t)jA * N_ELEM + ms[jA]) << 10));
            const uint4* cpB = reinterpret_cast<const uint4*>(
                g_w1t + (((size_t)jB * N_ELEM + ms[jB]) << 10));
            float sA, sB;
            DOT16(cpA, sA);
            DOT16(cpB, sB);
            // dual butterfly: lane0 -> sum(sA), lane1 -> sum(sB)
            float v   = (l & 1) ? sB : sA;
            float oth = (l & 1) ? sA : sB;
            v += __shfl_xor_sync(0xffffffffu, oth, 1);
            v += __shfl_xor_sync(0xffffffffu, v, 2);
            v += __shfl_xor_sync(0xffffffffu, v, 4);
            v += __shfl_xor_sync(0xffffffffu, v, 8);
            v += __shfl_xor_sync(0xffffffffu, v, 16);
            if (l < 2) midr[(l == 0) ? jA : jB] = fmaxf(v, 0.f);
        }
#undef DOT16
    }
    __syncthreads();

    // ---- Phase B ----
    {
        const int half = w >> 2;            // 0: j<64, 1: j>=64
        const int dbase = (w & 3) * 256 + l * 8;
        float a0 = 0.f, a1 = 0.f, a2 = 0.f, a3 = 0.f;
        float a4 = 0.f, a5 = 0.f, a6 = 0.f, a7 = 0.f;

#pragma unroll 4
        for (int jj = 0; jj < 64; jj++) {
            const int j = half * 64 + jj;
            const float r = midr[j];
            if (r > 0.f) {                       // warp-uniform
                const int m = ms[j];
                uint4 hv = *reinterpret_cast<const uint4*>(
                    g_w2h + (((size_t)m * D1 + j) << 10) + dbase);
                const __half2* hp = reinterpret_cast<const __half2*>(&hv);
                float2 f0 = __half22float2(hp[0]);
                float2 f1 = __half22float2(hp[1]);
                float2 f2 = __half22float2(hp[2]);
                float2 f3 = __half22float2(hp[3]);
                a0 = fmaf(r, f0.x, a0); a1 = fmaf(r, f0.y, a1);
                a2 = fmaf(r, f1.x, a2); a3 = fmaf(r, f1.y, a3);
                a4 = fmaf(r, f2.x, a4); a5 = fmaf(r, f2.y, a5);
                a6 = fmaf(r, f3.x, a6); a7 = fmaf(r, f3.y, a7);
            }
        }

        if (w < 4) {
            float4 v0 = make_float4(a0, a1, a2, a3);
            float4 v1 = make_float4(a4, a5, a6, a7);
            *reinterpret_cast<float4*>(res_s + dbase)     = v0;
            *reinterpret_cast<float4*>(res_s + dbase + 4) = v1;
        }
        __syncthreads();
        if (w >= 4) {
            float4 p0 = *reinterpret_cast<const float4*>(res_s + dbase);
            float4 p1 = *reinterpret_cast<const float4*>(res_s + dbase + 4);
            float4 bv0 = *reinterpret_cast<const float4*>(b2 + dbase);
            float4 bv1 = *reinterpret_cast<const float4*>(b2 + dbase + 4);
            float4 o0, o1;
            o0.x = a0 + p0.x + bv0.x; o0.y = a1 + p0.y + bv0.y;
            o0.z = a2 + p0.z + bv0.z; o0.w = a3 + p0.w + bv0.w;
            o1.x = a4 + p1.x + bv1.x; o1.y = a5 + p1.y + bv1.y;
            o1.z = a6 + p1.z + bv1.z; o1.w = a7 + p1.w + bv1.w;
            float* op = out_res + (size_t)b * D_MODEL + dbase;
            *reinterpret_cast<float4*>(op)     = o0;
            *reinterpret_cast<float4*>(op + 4) = o1;
        }
    }
}

// ---------------------------------------------------------------------------
extern "C" void kernel_launch(void* const* d_in, const int* in_sizes, int n_in,
                              void* d_out, int out_size) {
    const int*   qmask = nullptr;
    const float* x = nullptr, *w1 = nullptr, *w2 = nullptr, *b2 = nullptr;
    for (int i = 0; i < n_in; i++) {
        const int sz = in_sizes[i];
        if (sz == BATCH * D1)            qmask = (const int*)d_in[i];
        else if (sz == BATCH * D_MODEL)  x     = (const float*)d_in[i];
        else if (sz == D_MODEL)          b2    = (const float*)d_in[i];
        else if (sz == D_MODEL * D_FF) {
            if (!w1) w1 = (const float*)d_in[i];
            else     w2 = (const float*)d_in[i];
        }
    }

    float* out      = (float*)d_out;
    float* out_mask = nullptr;
    float* out_res  = out;
    if (out_size >= BATCH * D1 + BATCH * D_MODEL) {
        out_mask = out;
        out_res  = out + BATCH * D1;
    }

    prep_kernel<<<8192, 256>>>(w1, w2);
    fused_kernel<<<BATCH, 256>>>(qmask, x, b2, out_res, out_mask);
}

// round 6
// speedup vs baseline: 3.0418x; 1.1118x over previous
#include <cuda_runtime.h>
#include <cuda_fp16.h>
#include <cstdint>

#define D_MODEL 1024
#define D_FF    8192
#define N_ELEM  64
#define D1      128
#define BATCH   2048

__device__ __align__(16) __half g_w1t[(size_t)D_FF * D_MODEL];

// ---------------------------------------------------------------------------
// Prep: transpose+convert w1 (d, j, e) fp32 -> g_w1t[(j*64+e)*1024 + d] fp16.
// ---------------------------------------------------------------------------
__global__ __launch_bounds__(256) void prep_kernel(const float* __restrict__ w1) {
    __shared__ float tile[32][65];
    const int t = threadIdx.x;
    const int d0  = (blockIdx.x & 31) * 32;
    const int je0 = (blockIdx.x >> 5) * 64;
    const int dr = t >> 5;
    const int c  = (t & 31) * 2;
#pragma unroll
    for (int r = 0; r < 32; r += 8) {
        float2 v = *reinterpret_cast<const float2*>(
            w1 + (size_t)(d0 + r + dr) * D_FF + je0 + c);
        tile[r + dr][c]     = v.x;
        tile[r + dr][c + 1] = v.y;
    }
    __syncthreads();
    const int jl = t >> 2;
    const int ds = (t & 3) * 8;
    __half tmp[8];
#pragma unroll
    for (int i = 0; i < 8; i++) tmp[i] = __float2half_rn(tile[ds + i][jl]);
    *reinterpret_cast<uint4*>(g_w1t + (size_t)(je0 + jl) * D_MODEL + d0 + ds) =
        *reinterpret_cast<const uint4*>(tmp);
}

// ---------------------------------------------------------------------------
// Fused main kernel: one CTA per sample, 256 threads (8 warps).
// Phase A: warp w computes j = w*16..w*16+15 in pairs; x hoisted to regs as
//   fp16; column = 4x LDG.128; 16 HFMA2; dual-butterfly (2.5 shfl/j).
// Compaction: deterministic ballot-scan builds the active-j list (relu>0).
// Phase B: loop over ~64 active j, zero branches. w2 read as fp32 (original
//   input, d-contiguous). Each thread owns 4 outputs -> 1 LDG.128 +
//   2 packed fma.rn.f32x2 per j. No cvt, no smem combine.
// ---------------------------------------------------------------------------
__global__ __launch_bounds__(256) void fused_kernel(
    const int*   __restrict__ qmask,
    const float* __restrict__ x,
    const float* __restrict__ w2,
    const float* __restrict__ b2,
    float*       __restrict__ out_res,
    float*       __restrict__ out_mask)
{
    __shared__ __align__(16) __half x_h[D_MODEL];   // 2 KB
    __shared__ float midr[D1];
    __shared__ int   ms[D1];
    __shared__ float rv[D1];
    __shared__ int   offs_s[D1];
    __shared__ int   wcnt[4];

    const int b = blockIdx.x;
    const int t = threadIdx.x;
    const int w = t >> 5;
    const int l = t & 31;

    // stage x as fp16 + masks
    {
        float4 v = reinterpret_cast<const float4*>(x + (size_t)b * D_MODEL)[t];
        __half2 h0 = __floats2half2_rn(v.x, v.y);
        __half2 h1 = __floats2half2_rn(v.z, v.w);
        uint2 u;
        u.x = *reinterpret_cast<unsigned*>(&h0);
        u.y = *reinterpret_cast<unsigned*>(&h1);
        *reinterpret_cast<uint2*>(x_h + t * 4) = u;
    }
    if (t < D1) {
        int m = qmask[(size_t)b * D1 + t];
        ms[t] = m;
        if (out_mask) out_mask[(size_t)b * D1 + t] = (float)m;
    }
    __syncthreads();

    // ---- Phase A ----
    {
        const uint4* xh4 = reinterpret_cast<const uint4*>(x_h);
        const uint4 xv0 = xh4[l], xv1 = xh4[l + 32], xv2 = xh4[l + 64], xv3 = xh4[l + 96];
        const __half2* xA = reinterpret_cast<const __half2*>(&xv0);
        const __half2* xB = reinterpret_cast<const __half2*>(&xv1);
        const __half2* xC = reinterpret_cast<const __half2*>(&xv2);
        const __half2* xD = reinterpret_cast<const __half2*>(&xv3);

#define DOT16(cp, sOut)                                                        \
        {                                                                      \
            uint4 u0 = (cp)[l], u1 = (cp)[l + 32], u2 = (cp)[l + 64],          \
                  u3 = (cp)[l + 96];                                           \
            const __half2* cA = reinterpret_cast<const __half2*>(&u0);         \
            const __half2* cB = reinterpret_cast<const __half2*>(&u1);         \
            const __half2* cC = reinterpret_cast<const __half2*>(&u2);         \
            const __half2* cD = reinterpret_cast<const __half2*>(&u3);         \
            __half2 a0 = __hmul2(cA[0], xA[0]);                                \
            __half2 a1 = __hmul2(cA[1], xA[1]);                                \
            __half2 a2 = __hmul2(cA[2], xA[2]);                                \
            __half2 a3 = __hmul2(cA[3], xA[3]);                                \
            a0 = __hfma2(cB[0], xB[0], a0);                                    \
            a1 = __hfma2(cB[1], xB[1], a1);                                    \
            a2 = __hfma2(cB[2], xB[2], a2);                                    \
            a3 = __hfma2(cB[3], xB[3], a3);                                    \
            a0 = __hfma2(cC[0], xC[0], a0);                                    \
            a1 = __hfma2(cC[1], xC[1], a1);                                    \
            a2 = __hfma2(cC[2], xC[2], a2);                                    \
            a3 = __hfma2(cC[3], xC[3], a3);                                    \
            a0 = __hfma2(cD[0], xD[0], a0);                                    \
            a1 = __hfma2(cD[1], xD[1], a1);                                    \
            a2 = __hfma2(cD[2], xD[2], a2);                                    \
            a3 = __hfma2(cD[3], xD[3], a3);                                    \
            float2 f0 = __half22float2(a0);                                    \
            float2 f1 = __half22float2(a1);                                    \
            float2 f2 = __half22float2(a2);                                    \
            float2 f3 = __half22float2(a3);                                    \
            sOut = ((f0.x + f0.y) + (f1.x + f1.y)) +                           \
                   ((f2.x + f2.y) + (f3.x + f3.y));                            \
        }

#pragma unroll
        for (int p = 0; p < 8; p++) {
            const int jA = w * 16 + p;
            const int jB = jA + 8;
            const uint4* cpA = reinterpret_cast<const uint4*>(
                g_w1t + (((size_t)jA * N_ELEM + ms[jA]) << 10));
            const uint4* cpB = reinterpret_cast<const uint4*>(
                g_w1t + (((size_t)jB * N_ELEM + ms[jB]) << 10));
            float sA, sB;
            DOT16(cpA, sA);
            DOT16(cpB, sB);
            float v   = (l & 1) ? sB : sA;
            float oth = (l & 1) ? sA : sB;
            v += __shfl_xor_sync(0xffffffffu, oth, 1);
            v += __shfl_xor_sync(0xffffffffu, v, 2);
            v += __shfl_xor_sync(0xffffffffu, v, 4);
            v += __shfl_xor_sync(0xffffffffu, v, 8);
            v += __shfl_xor_sync(0xffffffffu, v, 16);
            if (l < 2) midr[(l == 0) ? jA : jB] = fmaxf(v, 0.f);
        }
#undef DOT16
    }
    __syncthreads();

    // ---- Compaction (deterministic, ordered by j) ----
    float cr = 0.f; bool act = false; int widx = 0;
    if (t < D1) {
        cr = midr[t];
        act = cr > 0.f;
        unsigned mb = __ballot_sync(0xffffffffu, act);
        widx = __popc(mb & ((1u << l) - 1u));
        if (l == 0) wcnt[w] = __popc(mb);
    }
    __syncthreads();
    const int nact = wcnt[0] + wcnt[1] + wcnt[2] + wcnt[3];
    if (act) {
        int base = 0;
#pragma unroll
        for (int q = 0; q < 3; q++) if (w > q) base += wcnt[q];
        rv[base + widx]     = cr;
        offs_s[base + widx] = (ms[t] * D1 + t) << 10;   // element offset into w2
    }
    __syncthreads();

    // ---- Phase B: each thread owns 4 outputs ----
    {
        const int dbase = t * 4;
        unsigned long long acc01 = 0ull, acc23 = 0ull;   // 2x f32x2 accumulators

#pragma unroll 4
        for (int k = 0; k < nact; k++) {
            const float r  = rv[k];
            const int  off = offs_s[k];
            float4 wv = *reinterpret_cast<const float4*>(w2 + off + dbase);
            unsigned long long w01, w23, rp;
            {
                unsigned ru = __float_as_uint(r);
                asm("mov.b64 %0, {%1, %1};" : "=l"(rp) : "r"(ru));
            }
            w01 = *reinterpret_cast<unsigned long long*>(&wv.x);
            w23 = *reinterpret_cast<unsigned long long*>(&wv.z);
            asm("fma.rn.f32x2 %0, %1, %2, %3;" : "=l"(acc01) : "l"(w01), "l"(rp), "l"(acc01));
            asm("fma.rn.f32x2 %0, %1, %2, %3;" : "=l"(acc23) : "l"(w23), "l"(rp), "l"(acc23));
        }

        float4 bv = reinterpret_cast<const float4*>(b2)[t];
        unsigned a0, a1, a2, a3;
        asm("mov.b64 {%0, %1}, %2;" : "=r"(a0), "=r"(a1) : "l"(acc01));
        asm("mov.b64 {%0, %1}, %2;" : "=r"(a2), "=r"(a3) : "l"(acc23));
        float4 o;
        o.x = __uint_as_float(a0) + bv.x;
        o.y = __uint_as_float(a1) + bv.y;
        o.z = __uint_as_float(a2) + bv.z;
        o.w = __uint_as_float(a3) + bv.w;
        reinterpret_cast<float4*>(out_res + (size_t)b * D_MODEL)[t] = o;
    }
}

// ---------------------------------------------------------------------------
extern "C" void kernel_launch(void* const* d_in, const int* in_sizes, int n_in,
                              void* d_out, int out_size) {
    const int*   qmask = nullptr;
    const float* x = nullptr, *w1 = nullptr, *w2 = nullptr, *b2 = nullptr;
    for (int i = 0; i < n_in; i++) {
        const int sz = in_sizes[i];
        if (sz == BATCH * D1)            qmask = (const int*)d_in[i];
        else if (sz == BATCH * D_MODEL)  x     = (const float*)d_in[i];
        else if (sz == D_MODEL)          b2    = (const float*)d_in[i];
        else if (sz == D_MODEL * D_FF) {
            if (!w1) w1 = (const float*)d_in[i];
            else     w2 = (const float*)d_in[i];
        }
    }

    float* out      = (float*)d_out;
    float* out_mask = nullptr;
    float* out_res  = out;
    if (out_size >= BATCH * D1 + BATCH * D_MODEL) {
        out_mask = out;
        out_res  = out + BATCH * D1;
    }

    prep_kernel<<<4096, 256>>>(w1);
    fused_kernel<<<BATCH, 256>>>(qmask, x, w2, b2, out_res, out_mask);
}